// round 5
// baseline (speedup 1.0000x reference)
#include <cuda_runtime.h>
#include <cstdint>

#define DEV __device__ __forceinline__

constexpr int D_EMB = 1024;
constexpr int NHEADS = 16;
constexpr int HDIM = 64;
constexpr int BB = 4;
constexpr int LSEQ = 2048;
constexpr int MTOT = BB * LSEQ; // 8192

// ---------------- static scratch (no allocations allowed) ----------------
constexpr size_t OFF_H   = 0;
constexpr size_t SZ_H    = (size_t)MTOT * D_EMB;                 // 8.39M
constexpr size_t OFF_QKV = OFF_H + SZ_H;
constexpr size_t SZ_QKV  = (size_t)MTOT * 3 * D_EMB;             // 25.2M
constexpr size_t OFF_ATT = OFF_QKV + SZ_QKV;
constexpr size_t SZ_ATT  = SZ_H;
constexpr size_t OFF_X1  = OFF_ATT + SZ_ATT;
constexpr size_t SZ_X1   = SZ_H;
constexpr size_t OFF_FC1 = OFF_X1 + SZ_X1;
constexpr size_t SZ_FC1  = (size_t)MTOT * 4 * D_EMB;             // 33.6M
constexpr size_t SCRATCH_TOTAL = OFF_FC1 + SZ_FC1;               // ~84M floats = 336MB

__device__ float g_scratch[SCRATCH_TOTAL];

// ---------------- rmsnorm ----------------
__global__ void rmsnorm_kernel(const float* __restrict__ x,
                               const float* __restrict__ scale,
                               float* __restrict__ out)
{
    int row = blockIdx.x;
    int t = threadIdx.x;
    const float4* xr = reinterpret_cast<const float4*>(x + (size_t)row * D_EMB);
    float4 v = xr[t];
    float ss = v.x*v.x + v.y*v.y + v.z*v.z + v.w*v.w;

    __shared__ float sred[8];
    #pragma unroll
    for (int o = 16; o > 0; o >>= 1) ss += __shfl_xor_sync(0xffffffffu, ss, o);
    int warp = t >> 5, lane = t & 31;
    if (lane == 0) sred[warp] = ss;
    __syncthreads();
    if (warp == 0) {
        float s2 = (lane < 8) ? sred[lane] : 0.f;
        #pragma unroll
        for (int o = 4; o > 0; o >>= 1) s2 += __shfl_xor_sync(0xffffffffu, s2, o);
        if (lane == 0) sred[0] = s2;
    }
    __syncthreads();
    float r = rsqrtf(sred[0] * (1.0f / D_EMB) + 1e-8f);
    float4 sc = reinterpret_cast<const float4*>(scale)[t];
    float4 o4 = make_float4(v.x*r*sc.x, v.y*r*sc.y, v.z*r*sc.z, v.w*r*sc.w);
    reinterpret_cast<float4*>(out + (size_t)row * D_EMB)[t] = o4;
}

// ---------------- TF32 mma helpers ----------------
DEV uint32_t f2tf(float x) {
    uint32_t r;
    asm("cvt.rna.tf32.f32 %0, %1;" : "=r"(r) : "f"(x));
    return r;
}

DEV void mma8(float* c, const uint32_t* a, const uint32_t* b) {
    asm volatile(
        "mma.sync.aligned.m16n8k8.row.col.f32.tf32.tf32.f32 "
        "{%0,%1,%2,%3}, {%4,%5,%6,%7}, {%8,%9}, {%0,%1,%2,%3};"
        : "+f"(c[0]), "+f"(c[1]), "+f"(c[2]), "+f"(c[3])
        : "r"(a[0]), "r"(a[1]), "r"(a[2]), "r"(a[3]), "r"(b[0]), "r"(b[1]));
}

// ---------------- fused flash attention ----------------
// Grid: (LSEQ/128, B*H). Block: 256 threads = 8 warps, each warp owns a
// 16-row Q strip. BC=128 key tile. Online softmax, P staged via smem
// (overlaid on the dead K tile region).
constexpr int QS = 68;   // smem row strides (floats), chosen conflict-free
constexpr int KS = 68;
constexpr int PS = 132;
constexpr int VS = 72;
constexpr int FLASH_SMEM_FLOATS = 128*QS + 128*PS + 128*VS; // 34816
constexpr int FLASH_SMEM_BYTES = FLASH_SMEM_FLOATS * 4;     // 139264

__global__ __launch_bounds__(256)
void flash_kernel(const float* __restrict__ qkv, float* __restrict__ att)
{
    extern __shared__ float sm[];
    float* sQ  = sm;                 // [128][QS]
    float* sKP = sm + 128 * QS;      // union: sK [128][KS]  /  sP [128][PS]
    float* sV  = sKP + 128 * PS;     // [128][VS]

    int bh = blockIdx.y;
    int b = bh >> 4, h = bh & 15;
    int qt = blockIdx.x;
    size_t rowbase = (size_t)b * LSEQ;
    const float* Qg = qkv + (rowbase + qt * 128) * 3072 + h * 64;
    const float* Kg = qkv + rowbase * 3072 + 1024 + h * 64;
    const float* Vg = qkv + rowbase * 3072 + 2048 + h * 64;

    int tid = threadIdx.x, warp = tid >> 5, lane = tid & 31;
    int g = lane >> 2, tg = lane & 3;
    int wm = warp * 16;

    // Load Q tile, pre-scaled by 1/sqrt(hd) = 0.125
    #pragma unroll
    for (int i = 0; i < 8; i++) {
        int lin = tid + i * 256;
        int r = lin >> 4, c4 = lin & 15;
        float4 v = *reinterpret_cast<const float4*>(Qg + (size_t)r * 3072 + c4 * 4);
        v.x *= 0.125f; v.y *= 0.125f; v.z *= 0.125f; v.w *= 0.125f;
        *reinterpret_cast<float4*>(&sQ[r * QS + c4 * 4]) = v;
    }

    float mrow[2] = {-1e30f, -1e30f};  // running max for rows g, g+8
    float lrow[2] = {0.f, 0.f};        // per-thread partial sums (quad-reduced at end)
    float O[8][4];                     // 16x64 output strip (mma C layout)
    #pragma unroll
    for (int i = 0; i < 8; i++)
        #pragma unroll
        for (int j = 0; j < 4; j++) O[i][j] = 0.f;

    for (int t = 0; t < LSEQ / 128; t++) {
        __syncthreads();   // previous iter done reading sP / sV
        // Load K, V tiles (natural [keypos][hd] layout)
        #pragma unroll
        for (int i = 0; i < 8; i++) {
            int lin = tid + i * 256;
            int r = lin >> 4, c4 = lin & 15;
            *reinterpret_cast<float4*>(&sKP[r * KS + c4 * 4]) =
                *reinterpret_cast<const float4*>(Kg + (size_t)(t * 128 + r) * 3072 + c4 * 4);
            *reinterpret_cast<float4*>(&sV[r * VS + c4 * 4]) =
                *reinterpret_cast<const float4*>(Vg + (size_t)(t * 128 + r) * 3072 + c4 * 4);
        }
        __syncthreads();

        // S = Qstrip @ K^T  (16 x 128 per warp)
        float sacc[16][4];
        #pragma unroll
        for (int nt = 0; nt < 16; nt++)
            #pragma unroll
            for (int q = 0; q < 4; q++) sacc[nt][q] = 0.f;

        #pragma unroll
        for (int ks = 0; ks < 64; ks += 8) {
            uint32_t aq[4];
            aq[0] = f2tf(sQ[(wm + g) * QS + ks + tg]);
            aq[1] = f2tf(sQ[(wm + g + 8) * QS + ks + tg]);
            aq[2] = f2tf(sQ[(wm + g) * QS + ks + tg + 4]);
            aq[3] = f2tf(sQ[(wm + g + 8) * QS + ks + tg + 4]);
            #pragma unroll
            for (int nt = 0; nt < 16; nt++) {
                uint32_t bk[2];
                bk[0] = f2tf(sKP[(nt * 8 + g) * KS + ks + tg]);
                bk[1] = f2tf(sKP[(nt * 8 + g) * KS + ks + tg + 4]);
                mma8(sacc[nt], aq, bk);
            }
        }
        __syncthreads();   // all warps done reading sK -> region becomes sP

        // Online softmax update (rows g and g+8 of the strip)
        float mnew[2] = {mrow[0], mrow[1]};
        #pragma unroll
        for (int nt = 0; nt < 16; nt++) {
            mnew[0] = fmaxf(mnew[0], fmaxf(sacc[nt][0], sacc[nt][1]));
            mnew[1] = fmaxf(mnew[1], fmaxf(sacc[nt][2], sacc[nt][3]));
        }
        #pragma unroll
        for (int o = 1; o <= 2; o <<= 1) {
            mnew[0] = fmaxf(mnew[0], __shfl_xor_sync(0xffffffffu, mnew[0], o));
            mnew[1] = fmaxf(mnew[1], __shfl_xor_sync(0xffffffffu, mnew[1], o));
        }
        float sf0 = __expf(mrow[0] - mnew[0]);
        float sf1 = __expf(mrow[1] - mnew[1]);
        mrow[0] = mnew[0]; mrow[1] = mnew[1];

        float ps0 = 0.f, ps1 = 0.f;
        #pragma unroll
        for (int nt = 0; nt < 16; nt++) {
            float p00 = __expf(sacc[nt][0] - mnew[0]);
            float p01 = __expf(sacc[nt][1] - mnew[0]);
            float p10 = __expf(sacc[nt][2] - mnew[1]);
            float p11 = __expf(sacc[nt][3] - mnew[1]);
            ps0 += p00 + p01;
            ps1 += p10 + p11;
            *reinterpret_cast<float2*>(&sKP[(wm + g) * PS + nt * 8 + 2 * tg]) =
                make_float2(p00, p01);
            *reinterpret_cast<float2*>(&sKP[(wm + g + 8) * PS + nt * 8 + 2 * tg]) =
                make_float2(p10, p11);
        }
        lrow[0] = lrow[0] * sf0 + ps0;
        lrow[1] = lrow[1] * sf1 + ps1;

        #pragma unroll
        for (int nt = 0; nt < 8; nt++) {
            O[nt][0] *= sf0; O[nt][1] *= sf0;
            O[nt][2] *= sf1; O[nt][3] *= sf1;
        }
        __syncwarp();      // sP strip visible within the owning warp

        // O += P @ V  (A frags from own sP strip, B frags from sV)
        #pragma unroll
        for (int ks = 0; ks < 128; ks += 8) {
            uint32_t ap[4];
            ap[0] = f2tf(sKP[(wm + g) * PS + ks + tg]);
            ap[1] = f2tf(sKP[(wm + g + 8) * PS + ks + tg]);
            ap[2] = f2tf(sKP[(wm + g) * PS + ks + tg + 4]);
            ap[3] = f2tf(sKP[(wm + g + 8) * PS + ks + tg + 4]);
            #pragma unroll
            for (int nt = 0; nt < 8; nt++) {
                uint32_t bv[2];
                bv[0] = f2tf(sV[(ks + tg) * VS + nt * 8 + g]);
                bv[1] = f2tf(sV[(ks + tg + 4) * VS + nt * 8 + g]);
                mma8(O[nt], ap, bv);
            }
        }
    }

    // Finalize: quad-reduce l, normalize, write out
    #pragma unroll
    for (int o = 1; o <= 2; o <<= 1) {
        lrow[0] += __shfl_xor_sync(0xffffffffu, lrow[0], o);
        lrow[1] += __shfl_xor_sync(0xffffffffu, lrow[1], o);
    }
    float inv0 = 1.0f / lrow[0];
    float inv1 = 1.0f / lrow[1];

    size_t row0 = (size_t)b * LSEQ + qt * 128 + wm + g;
    #pragma unroll
    for (int nt = 0; nt < 8; nt++) {
        int c = h * 64 + nt * 8 + 2 * tg;
        *reinterpret_cast<float2*>(att + row0 * D_EMB + c) =
            make_float2(O[nt][0] * inv0, O[nt][1] * inv0);
        *reinterpret_cast<float2*>(att + (row0 + 8) * D_EMB + c) =
            make_float2(O[nt][2] * inv1, O[nt][3] * inv1);
    }
}

// ---------------- TF32 warp-mma dense GEMM ----------------
enum { EPI_NONE = 0, EPI_RES = 1, EPI_GELU = 2 };

template<int EPI>
__global__ __launch_bounds__(256)
void gemm_kernel(const float* __restrict__ A, const float* __restrict__ B,
                 const float* __restrict__ Res, float* __restrict__ C,
                 int K, int lda, int ldb, int ldc)
{
    constexpr int BM = 128, BN = 128, BK = 16;
    constexpr int ASTR = 20;
    constexpr int BSTR = BN + 8;
    constexpr int WN = BN / 4;
    constexpr int NNT = WN / 8;

    __shared__ float As[BM * ASTR];
    __shared__ float Bs[BK * BSTR];

    int tid = threadIdx.x;
    int warp = tid >> 5, lane = tid & 31;
    int g = lane >> 2, tg = lane & 3;
    int wm = (warp >> 2) * 64;
    int wn = (warp & 3) * WN;
    int m0 = blockIdx.y * BM;
    int n0 = blockIdx.x * BN;

    float acc[4][NNT][4];
    #pragma unroll
    for (int i = 0; i < 4; i++)
        #pragma unroll
        for (int j = 0; j < NNT; j++)
            #pragma unroll
            for (int q = 0; q < 4; q++) acc[i][j][q] = 0.f;

    float4 aS[2], bS[2];

    auto loadA = [&](int kt) {
        #pragma unroll
        for (int i = 0; i < 2; i++) {
            int lin = tid + i * 256;
            int r = lin >> 2, c4 = lin & 3;
            aS[i] = *reinterpret_cast<const float4*>(
                A + (size_t)(m0 + r) * lda + kt * BK + c4 * 4);
        }
    };
    auto loadB = [&](int kt) {
        #pragma unroll
        for (int i = 0; i < 2; i++) {
            int lin = tid + i * 256;
            int r = lin / (BN / 4), c4 = lin % (BN / 4);
            bS[i] = *reinterpret_cast<const float4*>(
                B + (size_t)(kt * BK + r) * ldb + n0 + c4 * 4);
        }
    };
    auto storeAB = [&]() {
        #pragma unroll
        for (int i = 0; i < 2; i++) {
            int lin = tid + i * 256;
            int r = lin >> 2, c4 = lin & 3;
            *reinterpret_cast<float4*>(&As[r * ASTR + c4 * 4]) = aS[i];
        }
        #pragma unroll
        for (int i = 0; i < 2; i++) {
            int lin = tid + i * 256;
            int r = lin / (BN / 4), c4 = lin % (BN / 4);
            *reinterpret_cast<float4*>(&Bs[r * BSTR + c4 * 4]) = bS[i];
        }
    };

    int ntiles = K / BK;
    loadA(0); loadB(0);

    for (int kt = 0; kt < ntiles; kt++) {
        storeAB();
        __syncthreads();
        if (kt + 1 < ntiles) { loadA(kt + 1); loadB(kt + 1); }

        #pragma unroll
        for (int ks = 0; ks < BK; ks += 8) {
            uint32_t af[4][4], bf[NNT][2];
            #pragma unroll
            for (int mt = 0; mt < 4; mt++) {
                const float* ap = &As[(wm + mt * 16 + g) * ASTR + ks + tg];
                af[mt][0] = f2tf(ap[0]);
                af[mt][1] = f2tf(ap[8 * ASTR]);
                af[mt][2] = f2tf(ap[4]);
                af[mt][3] = f2tf(ap[8 * ASTR + 4]);
            }
            #pragma unroll
            for (int nt = 0; nt < NNT; nt++) {
                const float* bp = &Bs[(ks + tg) * BSTR + wn + nt * 8 + g];
                bf[nt][0] = f2tf(bp[0]);
                bf[nt][1] = f2tf(bp[4 * BSTR]);
            }
            #pragma unroll
            for (int mt = 0; mt < 4; mt++)
                #pragma unroll
                for (int nt = 0; nt < NNT; nt++)
                    mma8(acc[mt][nt], af[mt], bf[nt]);
        }
        __syncthreads();
    }

    #pragma unroll
    for (int mt = 0; mt < 4; mt++) {
        int r = m0 + wm + mt * 16 + g;
        #pragma unroll
        for (int nt = 0; nt < NNT; nt++) {
            int c = n0 + wn + nt * 8 + tg * 2;
            #pragma unroll
            for (int hh = 0; hh < 2; hh++) {
                int rr = r + hh * 8;
                float v0 = acc[mt][nt][2 * hh + 0];
                float v1 = acc[mt][nt][2 * hh + 1];
                if (EPI == EPI_RES) {
                    float2 rv = *reinterpret_cast<const float2*>(
                        Res + (size_t)rr * ldc + c);
                    v0 += rv.x; v1 += rv.y;
                } else if (EPI == EPI_GELU) {
                    v0 = 0.5f * v0 * (1.0f + erff(v0 * 0.70710678118654752f));
                    v1 = 0.5f * v1 * (1.0f + erff(v1 * 0.70710678118654752f));
                }
                *reinterpret_cast<float2*>(C + (size_t)rr * ldc + c) =
                    make_float2(v0, v1);
            }
        }
    }
}

// ---------------- launch ----------------
extern "C" void kernel_launch(void* const* d_in, const int* in_sizes, int n_in,
                              void* d_out, int out_size)
{
    const float* x     = (const float*)d_in[0];
    const float* n1s   = (const float*)d_in[1];
    const float* wqkv  = (const float*)d_in[2];
    const float* wproj = (const float*)d_in[3];
    const float* n2s   = (const float*)d_in[4];
    const float* wfc1  = (const float*)d_in[5];
    const float* wfc2  = (const float*)d_in[6];
    float* out = (float*)d_out;

    float* base = nullptr;
    cudaGetSymbolAddress((void**)&base, g_scratch);
    float* h   = base + OFF_H;
    float* qkv = base + OFF_QKV;
    float* att = base + OFF_ATT;
    float* x1  = base + OFF_X1;
    float* fc1 = base + OFF_FC1;

    cudaFuncSetAttribute(flash_kernel,
                         cudaFuncAttributeMaxDynamicSharedMemorySize,
                         FLASH_SMEM_BYTES);

    dim3 blk(256);

    // h = rmsnorm(x) * n1
    rmsnorm_kernel<<<MTOT, blk>>>(x, n1s, h);

    // qkv = h @ w_qkv   [8192 x 3072]
    gemm_kernel<EPI_NONE><<<dim3(3 * D_EMB / 128, MTOT / 128), blk>>>(
        h, wqkv, nullptr, qkv, D_EMB, D_EMB, 3 * D_EMB, 3 * D_EMB);

    // att = flash_attention(qkv)   [8192 x 1024]
    flash_kernel<<<dim3(LSEQ / 128, BB * NHEADS), blk, FLASH_SMEM_BYTES>>>(qkv, att);

    // x1 = x + att @ w_proj
    gemm_kernel<EPI_RES><<<dim3(D_EMB / 128, MTOT / 128), blk>>>(
        att, wproj, x, x1, D_EMB, D_EMB, D_EMB, D_EMB);

    // h = rmsnorm(x1) * n2
    rmsnorm_kernel<<<MTOT, blk>>>(x1, n2s, h);

    // fc1 = gelu(h @ w_fc1)   [8192 x 4096]
    gemm_kernel<EPI_GELU><<<dim3(4 * D_EMB / 128, MTOT / 128), blk>>>(
        h, wfc1, nullptr, fc1, D_EMB, D_EMB, 4 * D_EMB, 4 * D_EMB);

    // out = x1 + fc1 @ w_fc2
    gemm_kernel<EPI_RES><<<dim3(D_EMB / 128, MTOT / 128), blk>>>(
        fc1, wfc2, x1, out, 4 * D_EMB, 4 * D_EMB, D_EMB, D_EMB);
}

// round 9
// speedup vs baseline: 1.7993x; 1.7993x over previous
#include <cuda_runtime.h>
#include <cuda_fp16.h>
#include <cstdint>

#define DEV __device__ __forceinline__

constexpr int D_EMB = 1024;
constexpr int NHEADS = 16;
constexpr int HDIM = 64;
constexpr int BB = 4;
constexpr int LSEQ = 2048;
constexpr int MTOT = BB * LSEQ; // 8192

// ---------------- static scratch ----------------
constexpr size_t OFF_H   = 0;
constexpr size_t SZ_H    = (size_t)MTOT * D_EMB;
constexpr size_t OFF_QKV = OFF_H + SZ_H;
constexpr size_t SZ_QKV  = (size_t)MTOT * 3 * D_EMB;
constexpr size_t OFF_ATT = OFF_QKV + SZ_QKV;
constexpr size_t SZ_ATT  = SZ_H;
constexpr size_t OFF_X1  = OFF_ATT + SZ_ATT;
constexpr size_t SZ_X1   = SZ_H;
constexpr size_t OFF_FC1 = OFF_X1 + SZ_X1;
constexpr size_t SZ_FC1  = (size_t)MTOT * 4 * D_EMB;
constexpr size_t SCRATCH_TOTAL = OFF_FC1 + SZ_FC1;   // ~336MB

__device__ float g_scratch[SCRATCH_TOTAL];

// ---------------- rmsnorm ----------------
__global__ void rmsnorm_kernel(const float* __restrict__ x,
                               const float* __restrict__ scale,
                               float* __restrict__ out)
{
    int row = blockIdx.x;
    int t = threadIdx.x;
    const float4* xr = reinterpret_cast<const float4*>(x + (size_t)row * D_EMB);
    float4 v = xr[t];
    float ss = v.x*v.x + v.y*v.y + v.z*v.z + v.w*v.w;

    __shared__ float sred[8];
    #pragma unroll
    for (int o = 16; o > 0; o >>= 1) ss += __shfl_xor_sync(0xffffffffu, ss, o);
    int warp = t >> 5, lane = t & 31;
    if (lane == 0) sred[warp] = ss;
    __syncthreads();
    if (warp == 0) {
        float s2 = (lane < 8) ? sred[lane] : 0.f;
        #pragma unroll
        for (int o = 4; o > 0; o >>= 1) s2 += __shfl_xor_sync(0xffffffffu, s2, o);
        if (lane == 0) sred[0] = s2;
    }
    __syncthreads();
    float r = rsqrtf(sred[0] * (1.0f / D_EMB) + 1e-8f);
    float4 sc = reinterpret_cast<const float4*>(scale)[t];
    float4 o4 = make_float4(v.x*r*sc.x, v.y*r*sc.y, v.z*r*sc.z, v.w*r*sc.w);
    reinterpret_cast<float4*>(out + (size_t)row * D_EMB)[t] = o4;
}

// ---------------- mma / ldmatrix helpers ----------------
DEV void mma16(float* c, const uint32_t* a, const uint32_t* b) {
    asm volatile(
        "mma.sync.aligned.m16n8k16.row.col.f32.f16.f16.f32 "
        "{%0,%1,%2,%3}, {%4,%5,%6,%7}, {%8,%9}, {%0,%1,%2,%3};"
        : "+f"(c[0]), "+f"(c[1]), "+f"(c[2]), "+f"(c[3])
        : "r"(a[0]), "r"(a[1]), "r"(a[2]), "r"(a[3]), "r"(b[0]), "r"(b[1]));
}
DEV void ldsm4(uint32_t* r, uint32_t a) {
    asm volatile("ldmatrix.sync.aligned.m8n8.x4.shared.b16 {%0,%1,%2,%3}, [%4];"
        : "=r"(r[0]), "=r"(r[1]), "=r"(r[2]), "=r"(r[3]) : "r"(a));
}
DEV void ldsm2(uint32_t* r, uint32_t a) {
    asm volatile("ldmatrix.sync.aligned.m8n8.x2.shared.b16 {%0,%1}, [%2];"
        : "=r"(r[0]), "=r"(r[1]) : "r"(a));
}
DEV void ldsm2t(uint32_t* r, uint32_t a) {
    asm volatile("ldmatrix.sync.aligned.m8n8.x2.trans.shared.b16 {%0,%1}, [%2];"
        : "=r"(r[0]), "=r"(r[1]) : "r"(a));
}
DEV float ex2(float x) {
    float y;
    asm("ex2.approx.ftz.f32 %0, %1;" : "=f"(y) : "f"(x));
    return y;
}
DEV uint32_t cvta_s(const void* p) {
    return (uint32_t)__cvta_generic_to_shared(p);
}

// ---------------- fused flash attention (fp16 mma) ----------------
// Grid (LSEQ/128, B*H), 256 threads = 8 warps, warp owns 16-row Q strip.
constexpr int QS = 72, KS = 72, PS = 136, VS = 72; // half strides
constexpr int FL_BYTES = (128*QS + 128*PS + 128*VS) * 2;  // 71680

__global__ __launch_bounds__(256)
void flash_kernel(const float* __restrict__ qkv, float* __restrict__ att)
{
    extern __shared__ __half sh[];
    __half* sQ  = sh;                 // [128][QS]
    __half* sKP = sh + 128 * QS;      // K [128][KS]  union  P [128][PS]
    __half* sV  = sKP + 128 * PS;     // [128][VS]

    int bh = blockIdx.y;
    int b = bh >> 4, h = bh & 15;
    int qt = blockIdx.x;
    size_t rowbase = (size_t)b * LSEQ;
    const float* Qg = qkv + (rowbase + qt * 128) * 3072 + h * 64;
    const float* Kg = qkv + rowbase * 3072 + 1024 + h * 64;
    const float* Vg = qkv + rowbase * 3072 + 2048 + h * 64;

    int tid = threadIdx.x, warp = tid >> 5, lane = tid & 31;
    int g = lane >> 2, tg = lane & 3;
    int wm = warp * 16;
    int lr = (lane & 7) + ((lane & 8) ? 8 : 0);  // A-frag row
    int lk = (lane & 16) ? 8 : 0;                // A-frag k offset

    uint32_t uQ = cvta_s(sQ), uKP = cvta_s(sKP), uV = cvta_s(sV);

    // Load Q, scaled by 0.125 * log2(e) (exp2-domain softmax)
    const float QSCALE = 0.125f * 1.4426950408889634f;
    #pragma unroll
    for (int i = 0; i < 8; i++) {
        int lin = tid + i * 256;
        int r = lin >> 4, c4 = lin & 15;
        float4 v = *reinterpret_cast<const float4*>(Qg + (size_t)r * 3072 + c4 * 4);
        __half2 h0 = __floats2half2_rn(v.x * QSCALE, v.y * QSCALE);
        __half2 h1 = __floats2half2_rn(v.z * QSCALE, v.w * QSCALE);
        *reinterpret_cast<__half2*>(&sQ[r * QS + c4 * 4])     = h0;
        *reinterpret_cast<__half2*>(&sQ[r * QS + c4 * 4 + 2]) = h1;
    }

    float mrow[2] = {-1e30f, -1e30f};
    float lrow[2] = {0.f, 0.f};
    float O[8][4];
    #pragma unroll
    for (int i = 0; i < 8; i++)
        #pragma unroll
        for (int j = 0; j < 4; j++) O[i][j] = 0.f;

    for (int t = 0; t < LSEQ / 128; t++) {
        __syncthreads();   // prev iter done with sP / sV
        #pragma unroll
        for (int i = 0; i < 8; i++) {
            int lin = tid + i * 256;
            int r = lin >> 4, c4 = lin & 15;
            float4 kv = *reinterpret_cast<const float4*>(
                Kg + (size_t)(t * 128 + r) * 3072 + c4 * 4);
            float4 vv = *reinterpret_cast<const float4*>(
                Vg + (size_t)(t * 128 + r) * 3072 + c4 * 4);
            *reinterpret_cast<__half2*>(&sKP[r * KS + c4 * 4])     = __floats2half2_rn(kv.x, kv.y);
            *reinterpret_cast<__half2*>(&sKP[r * KS + c4 * 4 + 2]) = __floats2half2_rn(kv.z, kv.w);
            *reinterpret_cast<__half2*>(&sV[r * VS + c4 * 4])      = __floats2half2_rn(vv.x, vv.y);
            *reinterpret_cast<__half2*>(&sV[r * VS + c4 * 4 + 2])  = __floats2half2_rn(vv.z, vv.w);
        }
        __syncthreads();

        // S = Qstrip @ K^T   (16 x 128 per warp)
        float sacc[16][4];
        #pragma unroll
        for (int nt = 0; nt < 16; nt++)
            #pragma unroll
            for (int q = 0; q < 4; q++) sacc[nt][q] = 0.f;

        #pragma unroll
        for (int ks = 0; ks < 64; ks += 16) {
            uint32_t aq[4];
            ldsm4(aq, uQ + ((wm + lr) * QS + ks + lk) * 2);
            #pragma unroll
            for (int nt = 0; nt < 16; nt++) {
                uint32_t bk[2];
                ldsm2(bk, uKP + ((nt * 8 + (lane & 7)) * KS + ks + ((lane & 8) ? 8 : 0)) * 2);
                mma16(sacc[nt], aq, bk);
            }
        }
        __syncthreads();   // all warps done reading sK -> region becomes sP

        // online softmax (exp2 domain)
        float mnew[2] = {mrow[0], mrow[1]};
        #pragma unroll
        for (int nt = 0; nt < 16; nt++) {
            mnew[0] = fmaxf(mnew[0], fmaxf(sacc[nt][0], sacc[nt][1]));
            mnew[1] = fmaxf(mnew[1], fmaxf(sacc[nt][2], sacc[nt][3]));
        }
        #pragma unroll
        for (int o = 1; o <= 2; o <<= 1) {
            mnew[0] = fmaxf(mnew[0], __shfl_xor_sync(0xffffffffu, mnew[0], o));
            mnew[1] = fmaxf(mnew[1], __shfl_xor_sync(0xffffffffu, mnew[1], o));
        }
        float sf0 = ex2(mrow[0] - mnew[0]);
        float sf1 = ex2(mrow[1] - mnew[1]);
        mrow[0] = mnew[0]; mrow[1] = mnew[1];

        float ps0 = 0.f, ps1 = 0.f;
        #pragma unroll
        for (int nt = 0; nt < 16; nt++) {
            float p00 = ex2(sacc[nt][0] - mnew[0]);
            float p01 = ex2(sacc[nt][1] - mnew[0]);
            float p10 = ex2(sacc[nt][2] - mnew[1]);
            float p11 = ex2(sacc[nt][3] - mnew[1]);
            ps0 += p00 + p01;
            ps1 += p10 + p11;
            *reinterpret_cast<__half2*>(&sKP[(wm + g) * PS + nt * 8 + 2 * tg]) =
                __floats2half2_rn(p00, p01);
            *reinterpret_cast<__half2*>(&sKP[(wm + g + 8) * PS + nt * 8 + 2 * tg]) =
                __floats2half2_rn(p10, p11);
        }
        lrow[0] = lrow[0] * sf0 + ps0;
        lrow[1] = lrow[1] * sf1 + ps1;

        #pragma unroll
        for (int nt = 0; nt < 8; nt++) {
            O[nt][0] *= sf0; O[nt][1] *= sf0;
            O[nt][2] *= sf1; O[nt][3] *= sf1;
        }
        __syncwarp();   // own P strip visible (warp reads only its own rows)

        // O += P @ V
        #pragma unroll
        for (int ks = 0; ks < 128; ks += 16) {
            uint32_t ap[4];
            ldsm4(ap, uKP + ((wm + lr) * PS + ks + lk) * 2);
            #pragma unroll
            for (int nt = 0; nt < 8; nt++) {
                uint32_t bv[2];
                ldsm2t(bv, uV + ((ks + (lane & 15)) * VS + nt * 8) * 2);
                mma16(O[nt], ap, bv);
            }
        }
    }

    #pragma unroll
    for (int o = 1; o <= 2; o <<= 1) {
        lrow[0] += __shfl_xor_sync(0xffffffffu, lrow[0], o);
        lrow[1] += __shfl_xor_sync(0xffffffffu, lrow[1], o);
    }
    float inv0 = 1.0f / lrow[0];
    float inv1 = 1.0f / lrow[1];

    size_t row0 = (size_t)b * LSEQ + qt * 128 + wm + g;
    #pragma unroll
    for (int nt = 0; nt < 8; nt++) {
        int c = h * 64 + nt * 8 + 2 * tg;
        *reinterpret_cast<float2*>(att + row0 * D_EMB + c) =
            make_float2(O[nt][0] * inv0, O[nt][1] * inv0);
        *reinterpret_cast<float2*>(att + (row0 + 8) * D_EMB + c) =
            make_float2(O[nt][2] * inv1, O[nt][3] * inv1);
    }
}

// ---------------- fp16 warp-mma dense GEMM ----------------
enum { EPI_NONE = 0, EPI_RES = 1, EPI_GELU = 2 };

template<int EPI>
__global__ __launch_bounds__(256)
void gemm_kernel(const float* __restrict__ A, const float* __restrict__ B,
                 const float* __restrict__ Res, float* __restrict__ C,
                 int K, int lda, int ldb, int ldc)
{
    constexpr int BM = 128, BN = 128, BK = 16;
    constexpr int SA = 24;    // half stride, A rows (16 halves + pad)
    constexpr int SB = 136;   // half stride, B rows (128 halves + pad)

    __shared__ __half As[2][BM * SA];
    __shared__ __half Bs[2][BK * SB];

    int tid = threadIdx.x;
    int warp = tid >> 5, lane = tid & 31;
    int g = lane >> 2, tg = lane & 3;
    int wm = (warp >> 2) * 64;
    int wn = (warp & 3) * 32;
    int m0 = blockIdx.y * BM;
    int n0 = blockIdx.x * BN;
    int lr = (lane & 7) + ((lane & 8) ? 8 : 0);
    int lk = (lane & 16) ? 8 : 0;

    float acc[4][4][4];
    #pragma unroll
    for (int i = 0; i < 4; i++)
        #pragma unroll
        for (int j = 0; j < 4; j++)
            #pragma unroll
            for (int q = 0; q < 4; q++) acc[i][j][q] = 0.f;

    float4 aS[2], bS[2];

    auto loadg = [&](int kt) {
        #pragma unroll
        for (int i = 0; i < 2; i++) {
            int lin = tid + i * 256;
            int r = lin >> 2, c4 = lin & 3;
            aS[i] = *reinterpret_cast<const float4*>(
                A + (size_t)(m0 + r) * lda + kt * BK + c4 * 4);
        }
        #pragma unroll
        for (int i = 0; i < 2; i++) {
            int lin = tid + i * 256;
            int r = lin >> 5, c4 = lin & 31;
            bS[i] = *reinterpret_cast<const float4*>(
                B + (size_t)(kt * BK + r) * ldb + n0 + c4 * 4);
        }
    };
    auto stores = [&](int buf) {
        #pragma unroll
        for (int i = 0; i < 2; i++) {
            int lin = tid + i * 256;
            int r = lin >> 2, c4 = lin & 3;
            *reinterpret_cast<__half2*>(&As[buf][r * SA + c4 * 4]) =
                __floats2half2_rn(aS[i].x, aS[i].y);
            *reinterpret_cast<__half2*>(&As[buf][r * SA + c4 * 4 + 2]) =
                __floats2half2_rn(aS[i].z, aS[i].w);
        }
        #pragma unroll
        for (int i = 0; i < 2; i++) {
            int lin = tid + i * 256;
            int r = lin >> 5, c4 = lin & 31;
            *reinterpret_cast<__half2*>(&Bs[buf][r * SB + c4 * 4]) =
                __floats2half2_rn(bS[i].x, bS[i].y);
            *reinterpret_cast<__half2*>(&Bs[buf][r * SB + c4 * 4 + 2]) =
                __floats2half2_rn(bS[i].z, bS[i].w);
        }
    };

    int ntiles = K / BK;
    loadg(0);
    stores(0);
    __syncthreads();

    for (int kt = 0; kt < ntiles; kt++) {
        int buf = kt & 1;
        if (kt + 1 < ntiles) loadg(kt + 1);

        uint32_t uA = cvta_s(&As[buf][0]);
        uint32_t uB = cvta_s(&Bs[buf][0]);

        uint32_t af[4][4], bf[4][2];
        #pragma unroll
        for (int mt = 0; mt < 4; mt++)
            ldsm4(af[mt], uA + ((wm + mt * 16 + lr) * SA + lk) * 2);
        #pragma unroll
        for (int nt = 0; nt < 4; nt++)
            ldsm2t(bf[nt], uB + ((lane & 15) * SB + wn + nt * 8) * 2);
        #pragma unroll
        for (int mt = 0; mt < 4; mt++)
            #pragma unroll
            for (int nt = 0; nt < 4; nt++)
                mma16(acc[mt][nt], af[mt], bf[nt]);

        if (kt + 1 < ntiles) stores(buf ^ 1);
        __syncthreads();
    }

    #pragma unroll
    for (int mt = 0; mt < 4; mt++) {
        int r = m0 + wm + mt * 16 + g;
        #pragma unroll
        for (int nt = 0; nt < 4; nt++) {
            int c = n0 + wn + nt * 8 + tg * 2;
            #pragma unroll
            for (int hh = 0; hh < 2; hh++) {
                int rr = r + hh * 8;
                float v0 = acc[mt][nt][2 * hh + 0];
                float v1 = acc[mt][nt][2 * hh + 1];
                if (EPI == EPI_RES) {
                    float2 rv = *reinterpret_cast<const float2*>(
                        Res + (size_t)rr * ldc + c);
                    v0 += rv.x; v1 += rv.y;
                } else if (EPI == EPI_GELU) {
                    v0 = 0.5f * v0 * (1.0f + erff(v0 * 0.70710678118654752f));
                    v1 = 0.5f * v1 * (1.0f + erff(v1 * 0.70710678118654752f));
                }
                *reinterpret_cast<float2*>(C + (size_t)rr * ldc + c) =
                    make_float2(v0, v1);
            }
        }
    }
}

// ---------------- launch ----------------
extern "C" void kernel_launch(void* const* d_in, const int* in_sizes, int n_in,
                              void* d_out, int out_size)
{
    const float* x     = (const float*)d_in[0];
    const float* n1s   = (const float*)d_in[1];
    const float* wqkv  = (const float*)d_in[2];
    const float* wproj = (const float*)d_in[3];
    const float* n2s   = (const float*)d_in[4];
    const float* wfc1  = (const float*)d_in[5];
    const float* wfc2  = (const float*)d_in[6];
    float* out = (float*)d_out;

    float* base = nullptr;
    cudaGetSymbolAddress((void**)&base, g_scratch);
    float* h   = base + OFF_H;
    float* qkv = base + OFF_QKV;
    float* att = base + OFF_ATT;
    float* x1  = base + OFF_X1;
    float* fc1 = base + OFF_FC1;

    cudaFuncSetAttribute(flash_kernel,
                         cudaFuncAttributeMaxDynamicSharedMemorySize, FL_BYTES);

    dim3 blk(256);

    rmsnorm_kernel<<<MTOT, blk>>>(x, n1s, h);

    gemm_kernel<EPI_NONE><<<dim3(3 * D_EMB / 128, MTOT / 128), blk>>>(
        h, wqkv, nullptr, qkv, D_EMB, D_EMB, 3 * D_EMB, 3 * D_EMB);

    flash_kernel<<<dim3(LSEQ / 128, BB * NHEADS), blk, FL_BYTES>>>(qkv, att);

    gemm_kernel<EPI_RES><<<dim3(D_EMB / 128, MTOT / 128), blk>>>(
        att, wproj, x, x1, D_EMB, D_EMB, D_EMB, D_EMB);

    rmsnorm_kernel<<<MTOT, blk>>>(x1, n2s, h);

    gemm_kernel<EPI_GELU><<<dim3(4 * D_EMB / 128, MTOT / 128), blk>>>(
        h, wfc1, nullptr, fc1, D_EMB, D_EMB, 4 * D_EMB, 4 * D_EMB);

    gemm_kernel<EPI_RES><<<dim3(D_EMB / 128, MTOT / 128), blk>>>(
        fc1, wfc2, x1, out, 4 * D_EMB, 4 * D_EMB, D_EMB, D_EMB);
}

// round 12
// speedup vs baseline: 2.5039x; 1.3916x over previous
#include <cuda_runtime.h>
#include <cuda_fp16.h>
#include <cstdint>

#define DEV __device__ __forceinline__

constexpr int D_EMB = 1024;
constexpr int NHEADS = 16;
constexpr int HDIM = 64;
constexpr int BB = 4;
constexpr int LSEQ = 2048;
constexpr int MTOT = BB * LSEQ; // 8192

// ---------------- static scratch ----------------
__device__ float g_x1[(size_t)MTOT * D_EMB];

constexpr size_t HOFF_H    = 0;
constexpr size_t HSZ_H     = (size_t)MTOT * D_EMB;
constexpr size_t HOFF_QKV  = HOFF_H + HSZ_H;
constexpr size_t HSZ_QKV   = (size_t)MTOT * 3 * D_EMB;
constexpr size_t HOFF_ATT  = HOFF_QKV + HSZ_QKV;
constexpr size_t HSZ_ATT   = HSZ_H;
constexpr size_t HOFF_FC1  = HOFF_ATT + HSZ_ATT;
constexpr size_t HSZ_FC1   = (size_t)MTOT * 4 * D_EMB;
constexpr size_t HOFF_WQKV = HOFF_FC1 + HSZ_FC1;
constexpr size_t HSZ_WQKV  = (size_t)D_EMB * 3 * D_EMB;
constexpr size_t HOFF_WPRJ = HOFF_WQKV + HSZ_WQKV;
constexpr size_t HSZ_WPRJ  = (size_t)D_EMB * D_EMB;
constexpr size_t HOFF_WFC1 = HOFF_WPRJ + HSZ_WPRJ;
constexpr size_t HSZ_WFC1  = (size_t)D_EMB * 4 * D_EMB;
constexpr size_t HOFF_WFC2 = HOFF_WFC1 + HSZ_WFC1;
constexpr size_t HSZ_WFC2  = (size_t)4 * D_EMB * D_EMB;
constexpr size_t HTOTAL    = HOFF_WFC2 + HSZ_WFC2;

__device__ __half g_half[HTOTAL];

// ---------------- helpers ----------------
DEV void mma16(float* c, const uint32_t* a, const uint32_t* b) {
    asm volatile(
        "mma.sync.aligned.m16n8k16.row.col.f32.f16.f16.f32 "
        "{%0,%1,%2,%3}, {%4,%5,%6,%7}, {%8,%9}, {%0,%1,%2,%3};"
        : "+f"(c[0]), "+f"(c[1]), "+f"(c[2]), "+f"(c[3])
        : "r"(a[0]), "r"(a[1]), "r"(a[2]), "r"(a[3]), "r"(b[0]), "r"(b[1]));
}
DEV void ldsm4(uint32_t* r, uint32_t a) {
    asm volatile("ldmatrix.sync.aligned.m8n8.x4.shared.b16 {%0,%1,%2,%3}, [%4];"
        : "=r"(r[0]), "=r"(r[1]), "=r"(r[2]), "=r"(r[3]) : "r"(a));
}
DEV void ldsm2(uint32_t* r, uint32_t a) {
    asm volatile("ldmatrix.sync.aligned.m8n8.x2.shared.b16 {%0,%1}, [%2];"
        : "=r"(r[0]), "=r"(r[1]) : "r"(a));
}
DEV void ldsm2t(uint32_t* r, uint32_t a) {
    asm volatile("ldmatrix.sync.aligned.m8n8.x2.trans.shared.b16 {%0,%1}, [%2];"
        : "=r"(r[0]), "=r"(r[1]) : "r"(a));
}
DEV float ex2(float x) {
    float y; asm("ex2.approx.ftz.f32 %0, %1;" : "=f"(y) : "f"(x)); return y;
}
DEV uint32_t cvta_s(const void* p) { return (uint32_t)__cvta_generic_to_shared(p); }
DEV void cpasync16(uint32_t s, const void* g) {
    asm volatile("cp.async.cg.shared.global [%0], [%1], 16;" :: "r"(s), "l"(g));
}
DEV void cpcommit() { asm volatile("cp.async.commit_group;" ::: "memory"); }
template<int N> DEV void cpwait() {
    asm volatile("cp.async.wait_group %0;" :: "n"(N) : "memory");
}

// ---------------- weight fp32->fp16 ----------------
__global__ void f2h_kernel(const float* __restrict__ w, __half* __restrict__ o, int n4)
{
    int i = blockIdx.x * blockDim.x + threadIdx.x;
    if (i >= n4) return;
    float4 v = reinterpret_cast<const float4*>(w)[i];
    __half2 h0 = __floats2half2_rn(v.x, v.y);
    __half2 h1 = __floats2half2_rn(v.z, v.w);
    uint2 u;
    u.x = *reinterpret_cast<uint32_t*>(&h0);
    u.y = *reinterpret_cast<uint32_t*>(&h1);
    reinterpret_cast<uint2*>(o)[i] = u;
}

// ---------------- rmsnorm (fp32 in, fp16 out) ----------------
__global__ void rmsnorm_kernel(const float* __restrict__ x,
                               const float* __restrict__ scale,
                               __half* __restrict__ out)
{
    int row = blockIdx.x;
    int t = threadIdx.x;
    float4 v = reinterpret_cast<const float4*>(x + (size_t)row * D_EMB)[t];
    float ss = v.x*v.x + v.y*v.y + v.z*v.z + v.w*v.w;

    __shared__ float sred[8];
    #pragma unroll
    for (int o = 16; o > 0; o >>= 1) ss += __shfl_xor_sync(0xffffffffu, ss, o);
    int warp = t >> 5, lane = t & 31;
    if (lane == 0) sred[warp] = ss;
    __syncthreads();
    if (warp == 0) {
        float s2 = (lane < 8) ? sred[lane] : 0.f;
        #pragma unroll
        for (int o = 4; o > 0; o >>= 1) s2 += __shfl_xor_sync(0xffffffffu, s2, o);
        if (lane == 0) sred[0] = s2;
    }
    __syncthreads();
    float r = rsqrtf(sred[0] * (1.0f / D_EMB) + 1e-8f);
    float4 sc = reinterpret_cast<const float4*>(scale)[t];
    __half2 h0 = __floats2half2_rn(v.x*r*sc.x, v.y*r*sc.y);
    __half2 h1 = __floats2half2_rn(v.z*r*sc.z, v.w*r*sc.w);
    uint2 u;
    u.x = *reinterpret_cast<uint32_t*>(&h0);
    u.y = *reinterpret_cast<uint32_t*>(&h1);
    reinterpret_cast<uint2*>(out + (size_t)row * D_EMB)[t] = u;
}

// ---------------- fused flash attention (fp16 in/out) ----------------
constexpr int QS = 72, KS = 72, PS = 136, VS = 72;
constexpr int FL_BYTES = (128*QS + 128*PS + 128*VS) * 2;  // 71680

__global__ __launch_bounds__(256)
void flash_kernel(const __half* __restrict__ qkv, __half* __restrict__ att)
{
    extern __shared__ __half sh[];
    __half* sQ  = sh;
    __half* sKP = sh + 128 * QS;
    __half* sV  = sKP + 128 * PS;

    int bh = blockIdx.y;
    int b = bh >> 4, h = bh & 15;
    int qt = blockIdx.x;
    size_t rowbase = (size_t)b * LSEQ;
    const __half* Qg = qkv + (rowbase + qt * 128) * 3072 + h * 64;
    const __half* Kg = qkv + rowbase * 3072 + 1024 + h * 64;
    const __half* Vg = qkv + rowbase * 3072 + 2048 + h * 64;

    int tid = threadIdx.x, warp = tid >> 5, lane = tid & 31;
    int g = lane >> 2, tg = lane & 3;
    int wm = warp * 16;
    int lr = (lane & 7) + ((lane & 8) ? 8 : 0);
    int lk = (lane & 16) ? 8 : 0;

    uint32_t uQ = cvta_s(sQ), uKP = cvta_s(sKP), uV = cvta_s(sV);
    const float QSC = 0.125f * 1.4426950408889634f;  // scale * log2(e)

    // Load Q (raw halves; softmax scale applied post-mma)
    #pragma unroll
    for (int i = 0; i < 4; i++) {
        int lin = tid + i * 256;
        int r = lin >> 3, c8 = lin & 7;
        *reinterpret_cast<uint4*>(&sQ[r * QS + c8 * 8]) =
            *reinterpret_cast<const uint4*>(Qg + (size_t)r * 3072 + c8 * 8);
    }

    float mrow[2] = {-1e30f, -1e30f};
    float lrow[2] = {0.f, 0.f};
    float O[8][4];
    #pragma unroll
    for (int i = 0; i < 8; i++)
        #pragma unroll
        for (int j = 0; j < 4; j++) O[i][j] = 0.f;

    for (int t = 0; t < LSEQ / 128; t++) {
        __syncthreads();
        #pragma unroll
        for (int i = 0; i < 4; i++) {
            int lin = tid + i * 256;
            int r = lin >> 3, c8 = lin & 7;
            *reinterpret_cast<uint4*>(&sKP[r * KS + c8 * 8]) =
                *reinterpret_cast<const uint4*>(Kg + (size_t)(t * 128 + r) * 3072 + c8 * 8);
            *reinterpret_cast<uint4*>(&sV[r * VS + c8 * 8]) =
                *reinterpret_cast<const uint4*>(Vg + (size_t)(t * 128 + r) * 3072 + c8 * 8);
        }
        __syncthreads();

        float sacc[16][4];
        #pragma unroll
        for (int nt = 0; nt < 16; nt++)
            #pragma unroll
            for (int q = 0; q < 4; q++) sacc[nt][q] = 0.f;

        #pragma unroll
        for (int ks = 0; ks < 64; ks += 16) {
            uint32_t aq[4];
            ldsm4(aq, uQ + ((wm + lr) * QS + ks + lk) * 2);
            #pragma unroll
            for (int nt = 0; nt < 16; nt++) {
                uint32_t bk[2];
                ldsm2(bk, uKP + ((nt * 8 + (lane & 7)) * KS + ks + ((lane & 8) ? 8 : 0)) * 2);
                mma16(sacc[nt], aq, bk);
            }
        }
        __syncthreads();   // sK region becomes sP

        #pragma unroll
        for (int nt = 0; nt < 16; nt++) {
            sacc[nt][0] *= QSC; sacc[nt][1] *= QSC;
            sacc[nt][2] *= QSC; sacc[nt][3] *= QSC;
        }

        float mnew[2] = {mrow[0], mrow[1]};
        #pragma unroll
        for (int nt = 0; nt < 16; nt++) {
            mnew[0] = fmaxf(mnew[0], fmaxf(sacc[nt][0], sacc[nt][1]));
            mnew[1] = fmaxf(mnew[1], fmaxf(sacc[nt][2], sacc[nt][3]));
        }
        #pragma unroll
        for (int o = 1; o <= 2; o <<= 1) {
            mnew[0] = fmaxf(mnew[0], __shfl_xor_sync(0xffffffffu, mnew[0], o));
            mnew[1] = fmaxf(mnew[1], __shfl_xor_sync(0xffffffffu, mnew[1], o));
        }
        float sf0 = ex2(mrow[0] - mnew[0]);
        float sf1 = ex2(mrow[1] - mnew[1]);
        mrow[0] = mnew[0]; mrow[1] = mnew[1];

        float ps0 = 0.f, ps1 = 0.f;
        #pragma unroll
        for (int nt = 0; nt < 16; nt++) {
            float p00 = ex2(sacc[nt][0] - mnew[0]);
            float p01 = ex2(sacc[nt][1] - mnew[0]);
            float p10 = ex2(sacc[nt][2] - mnew[1]);
            float p11 = ex2(sacc[nt][3] - mnew[1]);
            ps0 += p00 + p01;
            ps1 += p10 + p11;
            *reinterpret_cast<__half2*>(&sKP[(wm + g) * PS + nt * 8 + 2 * tg]) =
                __floats2half2_rn(p00, p01);
            *reinterpret_cast<__half2*>(&sKP[(wm + g + 8) * PS + nt * 8 + 2 * tg]) =
                __floats2half2_rn(p10, p11);
        }
        lrow[0] = lrow[0] * sf0 + ps0;
        lrow[1] = lrow[1] * sf1 + ps1;

        #pragma unroll
        for (int nt = 0; nt < 8; nt++) {
            O[nt][0] *= sf0; O[nt][1] *= sf0;
            O[nt][2] *= sf1; O[nt][3] *= sf1;
        }
        __syncwarp();

        #pragma unroll
        for (int ks = 0; ks < 128; ks += 16) {
            uint32_t ap[4];
            ldsm4(ap, uKP + ((wm + lr) * PS + ks + lk) * 2);
            #pragma unroll
            for (int nt = 0; nt < 8; nt++) {
                uint32_t bv[2];
                ldsm2t(bv, uV + ((ks + (lane & 15)) * VS + nt * 8) * 2);
                mma16(O[nt], ap, bv);
            }
        }
    }

    #pragma unroll
    for (int o = 1; o <= 2; o <<= 1) {
        lrow[0] += __shfl_xor_sync(0xffffffffu, lrow[0], o);
        lrow[1] += __shfl_xor_sync(0xffffffffu, lrow[1], o);
    }
    float inv0 = 1.0f / lrow[0];
    float inv1 = 1.0f / lrow[1];

    size_t row0 = (size_t)b * LSEQ + qt * 128 + wm + g;
    #pragma unroll
    for (int nt = 0; nt < 8; nt++) {
        int c = h * 64 + nt * 8 + 2 * tg;
        *reinterpret_cast<__half2*>(att + row0 * D_EMB + c) =
            __floats2half2_rn(O[nt][0] * inv0, O[nt][1] * inv0);
        *reinterpret_cast<__half2*>(att + (row0 + 8) * D_EMB + c) =
            __floats2half2_rn(O[nt][2] * inv1, O[nt][3] * inv1);
    }
}

// ---------------- fp16 cp.async GEMM ----------------
enum { EPI_NONE = 0, EPI_RES = 1, EPI_GELU = 2 };

constexpr int GBM = 128, GBN = 128, GBK = 64;
constexpr int SA = 72;    // half stride A rows (64 + 8 pad)
constexpr int SB = 136;   // half stride B rows (128 + 8 pad)
constexpr int STAGE_A = GBM * SA;
constexpr int STAGE_B = GBK * SB;
constexpr int STAGE_H = STAGE_A + STAGE_B;
constexpr int GM_BYTES = 2 * STAGE_H * 2;    // 71680

template<int EPI, bool HOUT>
__global__ __launch_bounds__(256)
void gemm_h(const __half* __restrict__ A, const __half* __restrict__ B,
            const float* __restrict__ Res, void* __restrict__ Cv,
            int K, int lda, int ldb, int ldc)
{
    extern __shared__ __half smem[];
    __half* sA[2] = { smem, smem + STAGE_H };
    __half* sB[2] = { smem + STAGE_A, smem + STAGE_H + STAGE_A };

    int tid = threadIdx.x;
    int warp = tid >> 5, lane = tid & 31;
    int g = lane >> 2, tg = lane & 3;
    int wm = (warp >> 2) * 64;
    int wn = (warp & 3) * 32;
    int m0 = blockIdx.y * GBM;
    int n0 = blockIdx.x * GBN;
    int lr = (lane & 7) + ((lane & 8) ? 8 : 0);
    int lk = (lane & 16) ? 8 : 0;

    uint32_t uSA[2] = { cvta_s(sA[0]), cvta_s(sA[1]) };
    uint32_t uSB[2] = { cvta_s(sB[0]), cvta_s(sB[1]) };

    float acc[4][4][4];
    #pragma unroll
    for (int i = 0; i < 4; i++)
        #pragma unroll
        for (int j = 0; j < 4; j++)
            #pragma unroll
            for (int q = 0; q < 4; q++) acc[i][j][q] = 0.f;

    auto issue = [&](int kt, int buf) {
        // A tile: 128 rows x 64 halves = 1024 16B chunks -> 4/thread
        #pragma unroll
        for (int i = 0; i < 4; i++) {
            int id = tid + i * 256;
            int r = id >> 3, c = id & 7;
            cpasync16(uSA[buf] + (r * SA + c * 8) * 2,
                      A + (size_t)(m0 + r) * lda + kt * GBK + c * 8);
        }
        // B tile: 64 rows x 128 halves = 1024 16B chunks -> 4/thread
        #pragma unroll
        for (int i = 0; i < 4; i++) {
            int id = tid + i * 256;
            int r = id >> 4, c = id & 15;
            cpasync16(uSB[buf] + (r * SB + c * 8) * 2,
                      B + (size_t)(kt * GBK + r) * ldb + n0 + c * 8);
        }
        cpcommit();
    };

    int ntiles = K / GBK;
    issue(0, 0);

    for (int kt = 0; kt < ntiles; kt++) {
        int buf = kt & 1;
        if (kt + 1 < ntiles) {
            issue(kt + 1, buf ^ 1);
            cpwait<1>();
        } else {
            cpwait<0>();
        }
        __syncthreads();

        #pragma unroll
        for (int kk = 0; kk < GBK; kk += 16) {
            uint32_t af[4][4], bf[4][2];
            #pragma unroll
            for (int mt = 0; mt < 4; mt++)
                ldsm4(af[mt], uSA[buf] + ((wm + mt * 16 + lr) * SA + kk + lk) * 2);
            #pragma unroll
            for (int nt = 0; nt < 4; nt++)
                ldsm2t(bf[nt], uSB[buf] + ((kk + (lane & 15)) * SB + wn + nt * 8) * 2);
            #pragma unroll
            for (int mt = 0; mt < 4; mt++)
                #pragma unroll
                for (int nt = 0; nt < 4; nt++)
                    mma16(acc[mt][nt], af[mt], bf[nt]);
        }
        __syncthreads();
    }

    #pragma unroll
    for (int mt = 0; mt < 4; mt++) {
        int r = m0 + wm + mt * 16 + g;
        #pragma unroll
        for (int nt = 0; nt < 4; nt++) {
            int c = n0 + wn + nt * 8 + tg * 2;
            #pragma unroll
            for (int hh = 0; hh < 2; hh++) {
                int rr = r + hh * 8;
                float v0 = acc[mt][nt][2 * hh + 0];
                float v1 = acc[mt][nt][2 * hh + 1];
                if (EPI == EPI_RES) {
                    float2 rv = *reinterpret_cast<const float2*>(
                        Res + (size_t)rr * ldc + c);
                    v0 += rv.x; v1 += rv.y;
                } else if (EPI == EPI_GELU) {
                    v0 = 0.5f * v0 * (1.0f + erff(v0 * 0.70710678118654752f));
                    v1 = 0.5f * v1 * (1.0f + erff(v1 * 0.70710678118654752f));
                }
                if (HOUT) {
                    *reinterpret_cast<__half2*>(
                        (__half*)Cv + (size_t)rr * ldc + c) =
                        __floats2half2_rn(v0, v1);
                } else {
                    *reinterpret_cast<float2*>(
                        (float*)Cv + (size_t)rr * ldc + c) = make_float2(v0, v1);
                }
            }
        }
    }
}

// ---------------- launch ----------------
extern "C" void kernel_launch(void* const* d_in, const int* in_sizes, int n_in,
                              void* d_out, int out_size)
{
    const float* x     = (const float*)d_in[0];
    const float* n1s   = (const float*)d_in[1];
    const float* wqkv  = (const float*)d_in[2];
    const float* wproj = (const float*)d_in[3];
    const float* n2s   = (const float*)d_in[4];
    const float* wfc1  = (const float*)d_in[5];
    const float* wfc2  = (const float*)d_in[6];
    float* out = (float*)d_out;

    __half* hb = nullptr;
    cudaGetSymbolAddress((void**)&hb, g_half);
    float* x1 = nullptr;
    cudaGetSymbolAddress((void**)&x1, g_x1);

    __half* h    = hb + HOFF_H;
    __half* qkv  = hb + HOFF_QKV;
    __half* att  = hb + HOFF_ATT;
    __half* fc1  = hb + HOFF_FC1;
    __half* whq  = hb + HOFF_WQKV;
    __half* whp  = hb + HOFF_WPRJ;
    __half* wh1  = hb + HOFF_WFC1;
    __half* wh2  = hb + HOFF_WFC2;

    cudaFuncSetAttribute(flash_kernel,
        cudaFuncAttributeMaxDynamicSharedMemorySize, FL_BYTES);
    cudaFuncSetAttribute(gemm_h<EPI_NONE, true>,
        cudaFuncAttributeMaxDynamicSharedMemorySize, GM_BYTES);
    cudaFuncSetAttribute(gemm_h<EPI_RES, false>,
        cudaFuncAttributeMaxDynamicSharedMemorySize, GM_BYTES);
    cudaFuncSetAttribute(gemm_h<EPI_GELU, true>,
        cudaFuncAttributeMaxDynamicSharedMemorySize, GM_BYTES);

    dim3 blk(256);

    f2h_kernel<<<(int)(HSZ_WQKV / 4 / 256), blk>>>(wqkv,  whq, (int)(HSZ_WQKV / 4));
    f2h_kernel<<<(int)(HSZ_WPRJ / 4 / 256), blk>>>(wproj, whp, (int)(HSZ_WPRJ / 4));
    f2h_kernel<<<(int)(HSZ_WFC1 / 4 / 256), blk>>>(wfc1,  wh1, (int)(HSZ_WFC1 / 4));
    f2h_kernel<<<(int)(HSZ_WFC2 / 4 / 256), blk>>>(wfc2,  wh2, (int)(HSZ_WFC2 / 4));

    rmsnorm_kernel<<<MTOT, blk>>>(x, n1s, h);

    gemm_h<EPI_NONE, true><<<dim3(3 * D_EMB / GBN, MTOT / GBM), blk, GM_BYTES>>>(
        h, whq, nullptr, qkv, D_EMB, D_EMB, 3 * D_EMB, 3 * D_EMB);

    flash_kernel<<<dim3(LSEQ / 128, BB * NHEADS), blk, FL_BYTES>>>(qkv, att);

    gemm_h<EPI_RES, false><<<dim3(D_EMB / GBN, MTOT / GBM), blk, GM_BYTES>>>(
        att, whp, x, x1, D_EMB, D_EMB, D_EMB, D_EMB);

    rmsnorm_kernel<<<MTOT, blk>>>(x1, n2s, h);

    gemm_h<EPI_GELU, true><<<dim3(4 * D_EMB / GBN, MTOT / GBM), blk, GM_BYTES>>>(
        h, wh1, nullptr, fc1, D_EMB, D_EMB, 4 * D_EMB, 4 * D_EMB);

    gemm_h<EPI_RES, false><<<dim3(D_EMB / GBN, MTOT / GBM), blk, GM_BYTES>>>(
        fc1, wh2, x1, out, 4 * D_EMB, 4 * D_EMB, D_EMB, D_EMB);
}